// round 14
// baseline (speedup 1.0000x reference)
#include <cuda_runtime.h>

#define NN 100000
#define NE 1000000
#define CH 64
#define NG 1024

typedef unsigned long long ull;
typedef long long ll;

#define GEMM_BLOCKS ((NN + 255) / 256)          // 391
#define CSR_BLOCKS  ((NE / 4 + 255) / 256)      // 977

// ---- scratch (static __device__ — no allocations allowed) ----
__device__ int      g_is64;              // 1 if index arrays are int64, 0 if int32
__device__ int      g_degc[NN];
__device__ float    g_dinv[NN];
__device__ float    g_ginv[NG];          // 1/max(graph count,1)
__device__ int      g_rowptr[NN + 1];    // after CSR fill: rowptr[i] = end of row i
__device__ int      g_bsum[128];
__device__ int      g_csrc[NE];
__device__ unsigned g_yb[(size_t)NN * (CH / 2)];   // layer-1 y, bf16x2 packed
__device__ unsigned g_yb2[(size_t)NN * (CH / 2)];  // layer-2 y, bf16x2 packed
__device__ int      g_gcnt[NG];

// ---- packed fp32x2 helpers (sm_100+) ----
__device__ __forceinline__ ull ffma2(ull a, ull b, ull c) {
    ull d; asm("fma.rn.f32x2 %0, %1, %2, %3;" : "=l"(d) : "l"(a), "l"(b), "l"(c));
    return d;
}
__device__ __forceinline__ ull fmul2(ull a, ull b) {
    ull d; asm("mul.rn.f32x2 %0, %1, %2;" : "=l"(d) : "l"(a), "l"(b));
    return d;
}
__device__ __forceinline__ ull bcast2(float x) {
    ull r; asm("mov.b64 %0, {%1, %1};" : "=l"(r) : "f"(x));
    return r;
}
__device__ __forceinline__ float2 unpack2(ull v) {
    float2 f; asm("mov.b64 {%0, %1}, %2;" : "=f"(f.x), "=f"(f.y) : "l"(v));
    return f;
}
// pack two fp32 -> bf16x2 (lo in low half), round-to-nearest
__device__ __forceinline__ unsigned pk_bf16x2(float lo, float hi) {
    unsigned r; asm("cvt.rn.bf16x2.f32 %0, %1, %2;" : "=r"(r) : "f"(hi), "f"(lo));
    return r;
}

__device__ __forceinline__ int load_id(const void* p, ll i, int is64) {
    if (is64) return (int)((const ll*)p)[i];
    return ((const int*)p)[i];
}

// ---- fused: dtype detection + zero init + out prefill with bias ----
__global__ void k_init(const int* __restrict__ ei32, const float* __restrict__ bout,
                       float* __restrict__ out) {
    int i = blockIdx.x * blockDim.x + threadIdx.x;
    if (i < NN) g_degc[i] = 0;
    if (i < NG) { g_gcnt[i] = 0; out[i] = bout[0]; }
    if (blockIdx.x == 0) {
        // int64 little-endian => odd int32 words are the zero upper halves
        int z = (ei32[2 * threadIdx.x + 1] == 0) ? 1 : 0;
        int tot = __syncthreads_count(z);
        if (threadIdx.x == 0) g_is64 = (tot >= 200) ? 1 : 0;
    }
}

// ---- fused: degree histogram (4 edges/thread, 128-bit loads) + graph counts ----
__global__ void k_degcnt(const void* __restrict__ ei, const void* __restrict__ batch) {
    int t = blockIdx.x * blockDim.x + threadIdx.x;
    int is64 = g_is64;
    int e = t * 4;
    if (e < NE) {
        int d0, d1, d2, d3;
        if (is64) {
            const longlong2* dp = (const longlong2*)((const ll*)ei + NE);
            longlong2 va = __ldg(&dp[2 * t]);
            longlong2 vb = __ldg(&dp[2 * t + 1]);
            d0 = (int)va.x; d1 = (int)va.y; d2 = (int)vb.x; d3 = (int)vb.y;
        } else {
            int4 v = __ldg(&((const int4*)((const int*)ei + NE))[t]);
            d0 = v.x; d1 = v.y; d2 = v.z; d3 = v.w;
        }
        if ((unsigned)d0 < NN) atomicAdd(&g_degc[d0], 1);
        if ((unsigned)d1 < NN) atomicAdd(&g_degc[d1], 1);
        if ((unsigned)d2 < NN) atomicAdd(&g_degc[d2], 1);
        if ((unsigned)d3 < NN) atomicAdd(&g_degc[d3], 1);
    }
    if (t < NN) {
        int g = load_id(batch, t, is64);
        if ((unsigned)g < NG) {
            unsigned act = __activemask();
            unsigned m = __match_any_sync(act, g);
            int leader = __ffs(m) - 1;
            if ((int)(threadIdx.x & 31) == leader) atomicAdd(&g_gcnt[g], __popc(m));
        }
    }
}

// ---- scan stage 1: block-local exclusive scan of degree (shuffle-based) ----
__global__ void k_scan1() {
    __shared__ int wsum[32];
    int t = threadIdx.x;
    int i = blockIdx.x * 1024 + t;
    int v = (i < NN) ? g_degc[i] : 0;
    int s = v;
#pragma unroll
    for (int off = 1; off < 32; off <<= 1) {           // inclusive warp scan
        int n = __shfl_up_sync(0xffffffffu, s, off);
        if ((t & 31) >= off) s += n;
    }
    if ((t & 31) == 31) wsum[t >> 5] = s;
    __syncthreads();
    if (t < 32) {
        int w = wsum[t];
        int sw = w;
#pragma unroll
        for (int off = 1; off < 32; off <<= 1) {       // scan the 32 warp sums
            int n = __shfl_up_sync(0xffffffffu, sw, off);
            if (t >= off) sw += n;
        }
        wsum[t] = sw - w;                               // exclusive warp offset
        if (t == 31) g_bsum[blockIdx.x] = sw;           // block total
    }
    __syncthreads();
    if (i < NN) g_rowptr[i] = s - v + wsum[t >> 5];     // exclusive within block
}

// ---- scan stage 2 fused with apply + dinv + ginv (shuffle-based) ----
__global__ void k_scanapply() {
    __shared__ int bscan[128];
    __shared__ int woff[4];
    const int B = (NN + 1023) / 1024;                   // 98
    int t = threadIdx.x;                                // 256 threads
    int v = 0, s = 0;
    if (t < 128) {
        v = (t < B) ? g_bsum[t] : 0;
        s = v;
#pragma unroll
        for (int off = 1; off < 32; off <<= 1) {        // inclusive warp scan
            int n = __shfl_up_sync(0xffffffffu, s, off);
            if ((t & 31) >= off) s += n;
        }
        if ((t & 31) == 31) woff[t >> 5] = s;
    }
    __syncthreads();
    if (t < 128) {
        int p = 0;
#pragma unroll
        for (int w = 0; w < 3; w++)
            if (w < (t >> 5)) p += woff[w];
        bscan[t] = s - v + p;                           // exclusive over block sums
    }
    __syncthreads();

    int i = blockIdx.x * 256 + t;
    if (i < NN) {
        g_rowptr[i] = g_rowptr[i] + bscan[i >> 10];     // row start (pre-fill)
        g_dinv[i] = rsqrtf((float)g_degc[i] + 1.0f);
    }
    if (i < NG) g_ginv[i] = 1.0f / fmaxf((float)g_gcnt[i], 1.f);
}

// ---- heterogeneous: blocks [0,GEMM_BLOCKS) do GEMM1; rest do CSR fill ----
// GEMM1: y[i,:] = (x[i,:] @ W1) * dinv[i], bf16 out -> g_yb
// CSR:   atomically bump g_rowptr[dst] to place src (rowptr[i] becomes row end)
__global__ void __launch_bounds__(256) k_csrgemm1(const float* __restrict__ xin,
                                                  const float* __restrict__ W,
                                                  const void* __restrict__ ei) {
    if (blockIdx.x < GEMM_BLOCKS) {
        __shared__ __align__(16) float Ws[CH * CH];
        int tid = threadIdx.x;
        for (int i = tid; i < CH * CH / 4; i += 256)
            ((float4*)Ws)[i] = ((const float4*)W)[i];
        __syncthreads();

        int cg = tid & 7;            // col group: cols [cg*8, cg*8+8)
        int rg = tid >> 3;           // row group 0..31
        int row0 = blockIdx.x * 256 + rg * 8;

        ull acc[8][4];
#pragma unroll
        for (int r = 0; r < 8; r++)
#pragma unroll
            for (int c = 0; c < 4; c++) acc[r][c] = 0ull;

        int rl[8];
#pragma unroll
        for (int r = 0; r < 8; r++) {
            int rr = row0 + r;
            rl[r] = (rr < NN) ? rr : (NN - 1);
        }

        const ull* Ws2 = (const ull*)Ws;
        for (int k0 = 0; k0 < CH; k0 += 4) {
            float4 xv[8];
#pragma unroll
            for (int r = 0; r < 8; r++)
                xv[r] = __ldg((const float4*)(xin + (size_t)rl[r] * CH + k0));
#pragma unroll
            for (int kk = 0; kk < 4; kk++) {
                ull wv[4];
#pragma unroll
                for (int c = 0; c < 4; c++)
                    wv[c] = Ws2[(k0 + kk) * (CH / 2) + cg * 4 + c];
#pragma unroll
                for (int r = 0; r < 8; r++) {
                    float xk = (kk == 0) ? xv[r].x : (kk == 1) ? xv[r].y
                             : (kk == 2) ? xv[r].z : xv[r].w;
                    ull xk2 = bcast2(xk);
#pragma unroll
                    for (int c = 0; c < 4; c++)
                        acc[r][c] = ffma2(xk2, wv[c], acc[r][c]);
                }
            }
        }

#pragma unroll
        for (int r = 0; r < 8; r++) {
            int rr = row0 + r;
            if (rr < NN) {
                ull d2 = bcast2(g_dinv[rr]);
                unsigned w[4];
#pragma unroll
                for (int c = 0; c < 4; c++) {
                    float2 v = unpack2(fmul2(acc[r][c], d2));
                    w[c] = pk_bf16x2(v.x, v.y);
                }
                ((uint4*)(g_yb + (size_t)rr * (CH / 2)))[cg] =
                    make_uint4(w[0], w[1], w[2], w[3]);
            }
        }
    } else {
        int t = (blockIdx.x - GEMM_BLOCKS) * 256 + threadIdx.x;
        int e = t * 4;
        if (e >= NE) return;
        int is64 = g_is64;
        int s0, s1, s2, s3, d0, d1, d2, d3;
        if (is64) {
            const longlong2* sp = (const longlong2*)ei;
            const longlong2* dp = (const longlong2*)((const ll*)ei + NE);
            longlong2 sa = __ldg(&sp[2 * t]), sb = __ldg(&sp[2 * t + 1]);
            longlong2 da = __ldg(&dp[2 * t]), db = __ldg(&dp[2 * t + 1]);
            s0 = (int)sa.x; s1 = (int)sa.y; s2 = (int)sb.x; s3 = (int)sb.y;
            d0 = (int)da.x; d1 = (int)da.y; d2 = (int)db.x; d3 = (int)db.y;
        } else {
            int4 sv = __ldg(&((const int4*)ei)[t]);
            int4 dv = __ldg(&((const int4*)((const int*)ei + NE))[t]);
            s0 = sv.x; s1 = sv.y; s2 = sv.z; s3 = sv.w;
            d0 = dv.x; d1 = dv.y; d2 = dv.z; d3 = dv.w;
        }
        if ((unsigned)d0 < NN && (unsigned)s0 < NN) {
            int p = atomicAdd(&g_rowptr[d0], 1);
            if ((unsigned)p < NE) g_csrc[p] = s0;
        }
        if ((unsigned)d1 < NN && (unsigned)s1 < NN) {
            int p = atomicAdd(&g_rowptr[d1], 1);
            if ((unsigned)p < NE) g_csrc[p] = s1;
        }
        if ((unsigned)d2 < NN && (unsigned)s2 < NN) {
            int p = atomicAdd(&g_rowptr[d2], 1);
            if ((unsigned)p < NE) g_csrc[p] = s2;
        }
        if ((unsigned)d3 < NN && (unsigned)s3 < NN) {
            int p = atomicAdd(&g_rowptr[d3], 1);
            if ((unsigned)p < NE) g_csrc[p] = s3;
        }
    }
}

// bf16x2 word -> two fp32 (exact: shift into exponent position)
#define BF2X(w) __uint_as_float((w) << 16)
#define BF2Y(w) __uint_as_float((w) & 0xffff0000u)

// ---- fused layer-1 aggregate + GEMM2 ----
// per node-warp: h = relu(dinv*(sum y1[src] + y1[i]) + b1) (lane owns ch 2l,2l+1)
// then y2[i,:] = (h @ W2) * dinv[i] via shfl-broadcast mat-vec, bf16 -> g_yb2.
// Reads g_yb (layer-1), writes g_yb2 — no in-place race.
// After CSR fill, rowptr[i] = row end; start = i? rowptr[i-1] : 0.
__global__ void k_aggmm(const float* __restrict__ b,
                        const float* __restrict__ W2) {
    int i = (blockIdx.x * blockDim.x + threadIdx.x) >> 5;
    int lane = threadIdx.x & 31;
    if (i >= NN) return;

    const unsigned* __restrict__ yb = g_yb;
    unsigned ws = __ldg(&yb[(size_t)i * 32 + lane]);   // self loop
    float ax = BF2X(ws), ay = BF2Y(ws);
    int e = (i == 0) ? 0 : g_rowptr[i - 1];
    int end = g_rowptr[i];
    for (; e + 4 <= end; e += 4) {
        int s0 = g_csrc[e], s1 = g_csrc[e + 1], s2 = g_csrc[e + 2], s3 = g_csrc[e + 3];
        unsigned w0 = __ldg(&yb[(size_t)s0 * 32 + lane]);
        unsigned w1 = __ldg(&yb[(size_t)s1 * 32 + lane]);
        unsigned w2 = __ldg(&yb[(size_t)s2 * 32 + lane]);
        unsigned w3 = __ldg(&yb[(size_t)s3 * 32 + lane]);
        ax += (BF2X(w0) + BF2X(w1)) + (BF2X(w2) + BF2X(w3));
        ay += (BF2Y(w0) + BF2Y(w1)) + (BF2Y(w2) + BF2Y(w3));
    }
    for (; e < end; e++) {
        int s = g_csrc[e];
        unsigned w = __ldg(&yb[(size_t)s * 32 + lane]);
        ax += BF2X(w); ay += BF2Y(w);
    }
    float d = g_dinv[i];
    float2 bb = ((const float2*)b)[lane];
    float hx = fmaxf(fmaf(d, ax, bb.x), 0.f);          // h[2*lane]
    float hy = fmaxf(fmaf(d, ay, bb.y), 0.f);          // h[2*lane+1]

    // in-warp mat-vec: y2[c] = sum_k h[k] * W2[k][c], lane owns c = 2l, 2l+1
    const ull* __restrict__ W2p = (const ull*)W2;       // [k][32] packed col pairs
    ull acc2 = 0ull;
#pragma unroll 4
    for (int kp = 0; kp < 32; kp++) {
        float h0 = __shfl_sync(0xffffffffu, hx, kp);    // h[2*kp]
        float h1 = __shfl_sync(0xffffffffu, hy, kp);    // h[2*kp+1]
        ull w0 = __ldg(&W2p[(2 * kp) * 32 + lane]);
        ull w1 = __ldg(&W2p[(2 * kp + 1) * 32 + lane]);
        acc2 = ffma2(bcast2(h0), w0, acc2);
        acc2 = ffma2(bcast2(h1), w1, acc2);
    }
    float2 y2 = unpack2(fmul2(acc2, bcast2(d)));
    g_yb2[(size_t)i * 32 + lane] = pk_bf16x2(y2.x, y2.y);
}

// ---- layer-2 aggregate fused with Wout dot + mean-pool atomic into out ----
__global__ void k_agg2(const float* __restrict__ b,
                       const float* __restrict__ Wout,
                       const void* __restrict__ batch,
                       float* __restrict__ out) {
    int i = (blockIdx.x * blockDim.x + threadIdx.x) >> 5;
    int lane = threadIdx.x & 31;
    if (i >= NN) return;

    const unsigned* __restrict__ yb = g_yb2;
    unsigned ws = __ldg(&yb[(size_t)i * 32 + lane]);
    float ax = BF2X(ws), ay = BF2Y(ws);
    int e = (i == 0) ? 0 : g_rowptr[i - 1];
    int end = g_rowptr[i];
    for (; e + 4 <= end; e += 4) {
        int s0 = g_csrc[e], s1 = g_csrc[e + 1], s2 = g_csrc[e + 2], s3 = g_csrc[e + 3];
        unsigned w0 = __ldg(&yb[(size_t)s0 * 32 + lane]);
        unsigned w1 = __ldg(&yb[(size_t)s1 * 32 + lane]);
        unsigned w2 = __ldg(&yb[(size_t)s2 * 32 + lane]);
        unsigned w3 = __ldg(&yb[(size_t)s3 * 32 + lane]);
        ax += (BF2X(w0) + BF2X(w1)) + (BF2X(w2) + BF2X(w3));
        ay += (BF2Y(w0) + BF2Y(w1)) + (BF2Y(w2) + BF2Y(w3));
    }
    for (; e < end; e++) {
        int s = g_csrc[e];
        unsigned w = __ldg(&yb[(size_t)s * 32 + lane]);
        ax += BF2X(w); ay += BF2Y(w);
    }
    float d = g_dinv[i];
    float2 bb = ((const float2*)b)[lane];
    float hx = fmaxf(fmaf(d, ax, bb.x), 0.f);
    float hy = fmaxf(fmaf(d, ay, bb.y), 0.f);
    float2 wo = ((const float2*)Wout)[lane];
    float s = hx * wo.x + hy * wo.y;
#pragma unroll
    for (int off = 16; off; off >>= 1) s += __shfl_xor_sync(0xffffffffu, s, off);
    if (lane == 0) {
        int g = load_id(batch, i, g_is64);
        if ((unsigned)g < NG) atomicAdd(&out[g], s * g_ginv[g]);
    }
}

extern "C" void kernel_launch(void* const* d_in, const int* in_sizes, int n_in,
                              void* d_out, int out_size) {
    const float* x     = (const float*)d_in[0];
    const void*  ei    = d_in[1];
    const void*  batch = d_in[2];
    const float* W1    = (const float*)d_in[3];
    const float* b1    = (const float*)d_in[4];
    const float* W2    = (const float*)d_in[5];
    const float* b2    = (const float*)d_in[6];
    const float* Wout  = (const float*)d_in[7];
    const float* bout  = (const float*)d_in[8];
    float*       out   = (float*)d_out;

    (void)in_sizes; (void)n_in; (void)out_size;

    k_init     <<<(NN + 255) / 256, 256>>>((const int*)ei, bout, out);
    k_degcnt   <<<(NE / 4 + 255) / 256, 256>>>(ei, batch);
    k_scan1    <<<(NN + 1023) / 1024, 1024>>>();
    k_scanapply<<<(NN + 255) / 256, 256>>>();
    k_csrgemm1 <<<GEMM_BLOCKS + CSR_BLOCKS, 256>>>(x, W1, ei);   // GEMM1 ∥ CSR fill
    k_aggmm    <<<(NN * 32 + 255) / 256, 256>>>(b1, W2);         // agg1 + GEMM2
    k_agg2     <<<(NN * 32 + 255) / 256, 256>>>(b2, Wout, batch, out);
}

// round 16
// speedup vs baseline: 1.1897x; 1.1897x over previous
#include <cuda_runtime.h>

#define NN 100000
#define NE 1000000
#define CH 64
#define NG 1024

typedef unsigned long long ull;
typedef long long ll;

#define GEMM_BLOCKS ((NN + 255) / 256)          // 391
#define CSR_BLOCKS  ((NE / 2 + 255) / 256)      // 1954

// ---- scratch (static __device__ — no allocations allowed) ----
__device__ int      g_is64;              // 1 if index arrays are int64, 0 if int32
__device__ int      g_degc[NN];
__device__ float    g_dinv[NN];
__device__ float    g_ginv[NG];          // 1/max(graph count,1)
__device__ int      g_rowptr[NN];        // after CSR fill: rowptr[i] = end of row i
__device__ int      g_bsum[128];
__device__ int      g_csrc[NE];
__device__ unsigned g_yb[(size_t)NN * (CH / 2)];  // (h @ W) * dinv, bf16x2 packed
__device__ float    g_h[(size_t)NN * CH];         // hidden activations (fp32)
__device__ int      g_gcnt[NG];

// ---- packed fp32x2 helpers (sm_100+) ----
__device__ __forceinline__ ull ffma2(ull a, ull b, ull c) {
    ull d; asm("fma.rn.f32x2 %0, %1, %2, %3;" : "=l"(d) : "l"(a), "l"(b), "l"(c));
    return d;
}
__device__ __forceinline__ ull fmul2(ull a, ull b) {
    ull d; asm("mul.rn.f32x2 %0, %1, %2;" : "=l"(d) : "l"(a), "l"(b));
    return d;
}
__device__ __forceinline__ ull bcast2(float x) {
    ull r; asm("mov.b64 %0, {%1, %1};" : "=l"(r) : "f"(x));
    return r;
}
__device__ __forceinline__ float2 unpack2(ull v) {
    float2 f; asm("mov.b64 {%0, %1}, %2;" : "=f"(f.x), "=f"(f.y) : "l"(v));
    return f;
}
// pack two fp32 -> bf16x2 (lo in low half), round-to-nearest
__device__ __forceinline__ unsigned pk_bf16x2(float lo, float hi) {
    unsigned r; asm("cvt.rn.bf16x2.f32 %0, %1, %2;" : "=r"(r) : "f"(hi), "f"(lo));
    return r;
}

__device__ __forceinline__ int load_id(const void* p, ll i, int is64) {
    if (is64) return (int)((const ll*)p)[i];
    return ((const int*)p)[i];
}

// ---- fused: dtype detection + zero init + out prefill with bias ----
__global__ void k_init(const int* __restrict__ ei32, const float* __restrict__ bout,
                       float* __restrict__ out) {
    int i = blockIdx.x * blockDim.x + threadIdx.x;
    if (i < NN) g_degc[i] = 0;
    if (i < NG) { g_gcnt[i] = 0; out[i] = bout[0]; }
    if (blockIdx.x == 0) {
        // int64 little-endian => odd int32 words are the zero upper halves
        int z = (ei32[2 * threadIdx.x + 1] == 0) ? 1 : 0;
        int tot = __syncthreads_count(z);
        if (threadIdx.x == 0) g_is64 = (tot >= 200) ? 1 : 0;
    }
}

// ---- fused: degree histogram (2 edges/thread, vector loads) + graph counts ----
__global__ void k_degcnt(const void* __restrict__ ei, const void* __restrict__ batch) {
    int t = blockIdx.x * blockDim.x + threadIdx.x;
    int is64 = g_is64;
    int e = t * 2;
    if (e < NE) {
        int d0, d1;
        if (is64) {
            longlong2 v = __ldg(&((const longlong2*)((const ll*)ei + NE))[t]);
            d0 = (int)v.x; d1 = (int)v.y;
        } else {
            int2 v = __ldg(&((const int2*)((const int*)ei + NE))[t]);
            d0 = v.x; d1 = v.y;
        }
        if ((unsigned)d0 < NN) atomicAdd(&g_degc[d0], 1);
        if (e + 1 < NE && (unsigned)d1 < NN) atomicAdd(&g_degc[d1], 1);
    }
    if (t < NN) {
        int g = load_id(batch, t, is64);
        if ((unsigned)g < NG) {
            unsigned act = __activemask();
            unsigned m = __match_any_sync(act, g);
            int leader = __ffs(m) - 1;
            if ((int)(threadIdx.x & 31) == leader) atomicAdd(&g_gcnt[g], __popc(m));
        }
    }
}

// ---- scan stage 1: block-local exclusive scan of degree (shuffle-based) ----
__global__ void k_scan1() {
    __shared__ int wsum[32];
    int t = threadIdx.x;
    int i = blockIdx.x * 1024 + t;
    int v = (i < NN) ? g_degc[i] : 0;
    int s = v;
#pragma unroll
    for (int off = 1; off < 32; off <<= 1) {           // inclusive warp scan
        int n = __shfl_up_sync(0xffffffffu, s, off);
        if ((t & 31) >= off) s += n;
    }
    if ((t & 31) == 31) wsum[t >> 5] = s;
    __syncthreads();
    if (t < 32) {
        int w = wsum[t];
        int sw = w;
#pragma unroll
        for (int off = 1; off < 32; off <<= 1) {       // scan the 32 warp sums
            int n = __shfl_up_sync(0xffffffffu, sw, off);
            if (t >= off) sw += n;
        }
        wsum[t] = sw - w;                               // exclusive warp offset
        if (t == 31) g_bsum[blockIdx.x] = sw;           // block total
    }
    __syncthreads();
    if (i < NN) g_rowptr[i] = s - v + wsum[t >> 5];     // exclusive within block
}

// ---- scan stage 2 fused with apply + dinv + ginv (shuffle-based) ----
__global__ void k_scanapply() {
    __shared__ int bscan[128];
    __shared__ int woff[4];
    const int B = (NN + 1023) / 1024;                   // 98
    int t = threadIdx.x;                                // 256 threads
    int v = 0, s = 0;
    if (t < 128) {
        v = (t < B) ? g_bsum[t] : 0;
        s = v;
#pragma unroll
        for (int off = 1; off < 32; off <<= 1) {        // inclusive warp scan
            int n = __shfl_up_sync(0xffffffffu, s, off);
            if ((t & 31) >= off) s += n;
        }
        if ((t & 31) == 31) woff[t >> 5] = s;
    }
    __syncthreads();
    if (t < 128) {
        int p = 0;
#pragma unroll
        for (int w = 0; w < 3; w++)
            if (w < (t >> 5)) p += woff[w];
        bscan[t] = s - v + p;                           // exclusive over block sums
    }
    __syncthreads();

    int i = blockIdx.x * 256 + t;
    if (i < NN) {
        g_rowptr[i] = g_rowptr[i] + bscan[i >> 10];     // row start (pre-fill)
        g_dinv[i] = rsqrtf((float)g_degc[i] + 1.0f);
    }
    if (i < NG) g_ginv[i] = 1.0f / fmaxf((float)g_gcnt[i], 1.f);
}

// ---- heterogeneous: blocks [0,GEMM_BLOCKS) do GEMM1; rest do CSR fill ----
// GEMM1: y[i,:] = (x[i,:] @ W1) * dinv[i], bf16 out -> g_yb
// CSR:   atomically bump g_rowptr[dst] to place src (rowptr[i] becomes row end)
__global__ void __launch_bounds__(256) k_csrgemm1(const float* __restrict__ xin,
                                                  const float* __restrict__ W,
                                                  const void* __restrict__ ei) {
    if (blockIdx.x < GEMM_BLOCKS) {
        __shared__ __align__(16) float Ws[CH * CH];
        int tid = threadIdx.x;
        for (int i = tid; i < CH * CH / 4; i += 256)
            ((float4*)Ws)[i] = ((const float4*)W)[i];
        __syncthreads();

        int cg = tid & 7;            // col group: cols [cg*8, cg*8+8)
        int rg = tid >> 3;           // row group 0..31
        int row0 = blockIdx.x * 256 + rg * 8;

        ull acc[8][4];
#pragma unroll
        for (int r = 0; r < 8; r++)
#pragma unroll
            for (int c = 0; c < 4; c++) acc[r][c] = 0ull;

        int rl[8];
#pragma unroll
        for (int r = 0; r < 8; r++) {
            int rr = row0 + r;
            rl[r] = (rr < NN) ? rr : (NN - 1);
        }

        const ull* Ws2 = (const ull*)Ws;
        for (int k0 = 0; k0 < CH; k0 += 4) {
            float4 xv[8];
#pragma unroll
            for (int r = 0; r < 8; r++)
                xv[r] = __ldg((const float4*)(xin + (size_t)rl[r] * CH + k0));
#pragma unroll
            for (int kk = 0; kk < 4; kk++) {
                ull wv[4];
#pragma unroll
                for (int c = 0; c < 4; c++)
                    wv[c] = Ws2[(k0 + kk) * (CH / 2) + cg * 4 + c];
#pragma unroll
                for (int r = 0; r < 8; r++) {
                    float xk = (kk == 0) ? xv[r].x : (kk == 1) ? xv[r].y
                             : (kk == 2) ? xv[r].z : xv[r].w;
                    ull xk2 = bcast2(xk);
#pragma unroll
                    for (int c = 0; c < 4; c++)
                        acc[r][c] = ffma2(xk2, wv[c], acc[r][c]);
                }
            }
        }

#pragma unroll
        for (int r = 0; r < 8; r++) {
            int rr = row0 + r;
            if (rr < NN) {
                ull d2 = bcast2(g_dinv[rr]);
                unsigned w[4];
#pragma unroll
                for (int c = 0; c < 4; c++) {
                    float2 v = unpack2(fmul2(acc[r][c], d2));
                    w[c] = pk_bf16x2(v.x, v.y);
                }
                ((uint4*)(g_yb + (size_t)rr * (CH / 2)))[cg] =
                    make_uint4(w[0], w[1], w[2], w[3]);
            }
        }
    } else {
        int t = (blockIdx.x - GEMM_BLOCKS) * 256 + threadIdx.x;
        int e = t * 2;
        if (e >= NE) return;
        int is64 = g_is64;
        int s0, s1, d0, d1;
        if (is64) {
            longlong2 sv = __ldg(&((const longlong2*)ei)[t]);
            longlong2 dv = __ldg(&((const longlong2*)((const ll*)ei + NE))[t]);
            s0 = (int)sv.x; s1 = (int)sv.y; d0 = (int)dv.x; d1 = (int)dv.y;
        } else {
            int2 sv = __ldg(&((const int2*)ei)[t]);
            int2 dv = __ldg(&((const int2*)((const int*)ei + NE))[t]);
            s0 = sv.x; s1 = sv.y; d0 = dv.x; d1 = dv.y;
        }
        if ((unsigned)d0 < NN && (unsigned)s0 < NN) {
            int p = atomicAdd(&g_rowptr[d0], 1);
            if ((unsigned)p < NE) g_csrc[p] = s0;
        }
        if (e + 1 < NE && (unsigned)d1 < NN && (unsigned)s1 < NN) {
            int p = atomicAdd(&g_rowptr[d1], 1);
            if ((unsigned)p < NE) g_csrc[p] = s1;
        }
    }
}

// bf16x2 word -> two fp32 (exact: shift into exponent position)
#define BF2X(w) __uint_as_float((w) << 16)
#define BF2Y(w) __uint_as_float((w) & 0xffff0000u)

// ---- layer-1 aggregate: h[i] = relu(dinv[i]*(sum_in y[src] + y[i]) + b1) ----
// one warp per node, each lane owns 2 channels (one bf16x2 word per edge)
// After CSR fill, rowptr[i] = row end; start = i? rowptr[i-1] : 0.
__global__ void k_agg1(const float* __restrict__ b) {
    int i = (blockIdx.x * blockDim.x + threadIdx.x) >> 5;
    int lane = threadIdx.x & 31;
    if (i >= NN) return;

    const unsigned* __restrict__ yb = g_yb;
    unsigned ws = __ldg(&yb[(size_t)i * 32 + lane]);   // self loop
    float ax = BF2X(ws), ay = BF2Y(ws);
    int e = (i == 0) ? 0 : g_rowptr[i - 1];
    int end = g_rowptr[i];
    for (; e + 4 <= end; e += 4) {
        int s0 = g_csrc[e], s1 = g_csrc[e + 1], s2 = g_csrc[e + 2], s3 = g_csrc[e + 3];
        unsigned w0 = __ldg(&yb[(size_t)s0 * 32 + lane]);
        unsigned w1 = __ldg(&yb[(size_t)s1 * 32 + lane]);
        unsigned w2 = __ldg(&yb[(size_t)s2 * 32 + lane]);
        unsigned w3 = __ldg(&yb[(size_t)s3 * 32 + lane]);
        ax += (BF2X(w0) + BF2X(w1)) + (BF2X(w2) + BF2X(w3));
        ay += (BF2Y(w0) + BF2Y(w1)) + (BF2Y(w2) + BF2Y(w3));
    }
    for (; e < end; e++) {
        int s = g_csrc[e];
        unsigned w = __ldg(&yb[(size_t)s * 32 + lane]);
        ax += BF2X(w); ay += BF2Y(w);
    }
    float d = g_dinv[i];
    float2 bb = ((const float2*)b)[lane];
    float2 h;
    h.x = fmaxf(fmaf(d, ax, bb.x), 0.f);
    h.y = fmaxf(fmaf(d, ay, bb.y), 0.f);
    ((float2*)(g_h + (size_t)i * CH))[lane] = h;
}

// ---- GEMM2: y[i,:] = (g_h[i,:] @ W2) * dinv[i], tiled FFMA2, bf16 -> g_yb ----
// Safe overwrite of g_yb: y2[i] depends only on g_h (fully written before launch).
__global__ void __launch_bounds__(256) k_gemm2(const float* __restrict__ W) {
    __shared__ __align__(16) float Ws[CH * CH];
    const float* in = (const float*)g_h;
    int tid = threadIdx.x;
    for (int i = tid; i < CH * CH / 4; i += 256)
        ((float4*)Ws)[i] = ((const float4*)W)[i];
    __syncthreads();

    int cg = tid & 7;
    int rg = tid >> 3;
    int row0 = blockIdx.x * 256 + rg * 8;

    ull acc[8][4];
#pragma unroll
    for (int r = 0; r < 8; r++)
#pragma unroll
        for (int c = 0; c < 4; c++) acc[r][c] = 0ull;

    int rl[8];
#pragma unroll
    for (int r = 0; r < 8; r++) {
        int rr = row0 + r;
        rl[r] = (rr < NN) ? rr : (NN - 1);
    }

    const ull* Ws2 = (const ull*)Ws;
    for (int k0 = 0; k0 < CH; k0 += 4) {
        float4 xv[8];
#pragma unroll
        for (int r = 0; r < 8; r++)
            xv[r] = __ldg((const float4*)(in + (size_t)rl[r] * CH + k0));
#pragma unroll
        for (int kk = 0; kk < 4; kk++) {
            ull wv[4];
#pragma unroll
            for (int c = 0; c < 4; c++)
                wv[c] = Ws2[(k0 + kk) * (CH / 2) + cg * 4 + c];
#pragma unroll
            for (int r = 0; r < 8; r++) {
                float xk = (kk == 0) ? xv[r].x : (kk == 1) ? xv[r].y
                         : (kk == 2) ? xv[r].z : xv[r].w;
                ull xk2 = bcast2(xk);
#pragma unroll
                for (int c = 0; c < 4; c++)
                    acc[r][c] = ffma2(xk2, wv[c], acc[r][c]);
            }
        }
    }

#pragma unroll
    for (int r = 0; r < 8; r++) {
        int rr = row0 + r;
        if (rr < NN) {
            ull d2 = bcast2(g_dinv[rr]);
            unsigned w[4];
#pragma unroll
            for (int c = 0; c < 4; c++) {
                float2 v = unpack2(fmul2(acc[r][c], d2));
                w[c] = pk_bf16x2(v.x, v.y);
            }
            ((uint4*)(g_yb + (size_t)rr * (CH / 2)))[cg] =
                make_uint4(w[0], w[1], w[2], w[3]);
        }
    }
}

// ---- layer-2 aggregate fused with Wout dot + mean-pool atomic into out ----
__global__ void k_agg2(const float* __restrict__ b,
                       const float* __restrict__ Wout,
                       const void* __restrict__ batch,
                       float* __restrict__ out) {
    int i = (blockIdx.x * blockDim.x + threadIdx.x) >> 5;
    int lane = threadIdx.x & 31;
    if (i >= NN) return;

    const unsigned* __restrict__ yb = g_yb;
    unsigned ws = __ldg(&yb[(size_t)i * 32 + lane]);
    float ax = BF2X(ws), ay = BF2Y(ws);
    int e = (i == 0) ? 0 : g_rowptr[i - 1];
    int end = g_rowptr[i];
    for (; e + 4 <= end; e += 4) {
        int s0 = g_csrc[e], s1 = g_csrc[e + 1], s2 = g_csrc[e + 2], s3 = g_csrc[e + 3];
        unsigned w0 = __ldg(&yb[(size_t)s0 * 32 + lane]);
        unsigned w1 = __ldg(&yb[(size_t)s1 * 32 + lane]);
        unsigned w2 = __ldg(&yb[(size_t)s2 * 32 + lane]);
        unsigned w3 = __ldg(&yb[(size_t)s3 * 32 + lane]);
        ax += (BF2X(w0) + BF2X(w1)) + (BF2X(w2) + BF2X(w3));
        ay += (BF2Y(w0) + BF2Y(w1)) + (BF2Y(w2) + BF2Y(w3));
    }
    for (; e < end; e++) {
        int s = g_csrc[e];
        unsigned w = __ldg(&yb[(size_t)s * 32 + lane]);
        ax += BF2X(w); ay += BF2Y(w);
    }
    float d = g_dinv[i];
    float2 bb = ((const float2*)b)[lane];
    float hx = fmaxf(fmaf(d, ax, bb.x), 0.f);
    float hy = fmaxf(fmaf(d, ay, bb.y), 0.f);
    float2 wo = ((const float2*)Wout)[lane];
    float s = hx * wo.x + hy * wo.y;
#pragma unroll
    for (int off = 16; off; off >>= 1) s += __shfl_xor_sync(0xffffffffu, s, off);
    if (lane == 0) {
        int g = load_id(batch, i, g_is64);
        if ((unsigned)g < NG) atomicAdd(&out[g], s * g_ginv[g]);
    }
}

extern "C" void kernel_launch(void* const* d_in, const int* in_sizes, int n_in,
                              void* d_out, int out_size) {
    const float* x     = (const float*)d_in[0];
    const void*  ei    = d_in[1];
    const void*  batch = d_in[2];
    const float* W1    = (const float*)d_in[3];
    const float* b1    = (const float*)d_in[4];
    const float* W2    = (const float*)d_in[5];
    const float* b2    = (const float*)d_in[6];
    const float* Wout  = (const float*)d_in[7];
    const float* bout  = (const float*)d_in[8];
    float*       out   = (float*)d_out;

    (void)in_sizes; (void)n_in; (void)out_size;

    k_init     <<<(NN + 255) / 256, 256>>>((const int*)ei, bout, out);
    k_degcnt   <<<(NE / 2 + 255) / 256, 256>>>(ei, batch);
    k_scan1    <<<(NN + 1023) / 1024, 1024>>>();
    k_scanapply<<<(NN + 255) / 256, 256>>>();
    k_csrgemm1 <<<GEMM_BLOCKS + CSR_BLOCKS, 256>>>(x, W1, ei);   // GEMM1 ∥ CSR fill
    k_agg1     <<<(NN * 32 + 255) / 256, 256>>>(b1);
    k_gemm2    <<<(NN + 255) / 256, 256>>>(W2);
    k_agg2     <<<(NN * 32 + 255) / 256, 256>>>(b2, Wout, batch, out);
}

// round 17
// speedup vs baseline: 1.2275x; 1.0317x over previous
#include <cuda_runtime.h>

#define NN 100000
#define NE 1000000
#define CH 64
#define NG 1024

typedef unsigned long long ull;
typedef long long ll;

#define GEMM_BLOCKS ((NN + 255) / 256)          // 391
#define CSR_BLOCKS  ((NE / 2 + 255) / 256)      // 1954

// ---- scratch (static __device__ — zero at module load; invariants keep them
//      "ready" at every call start: consumers re-zero for the next call) ----
__device__ int      g_is64;              // set by k_degcnt each call
__device__ int      g_degc[NN];          // zero at call start (agg2 re-zeros)
__device__ float    g_dinv[NN];
__device__ float    g_ginv[NG];
__device__ int      g_rowptr[NN];        // scanoff: row start; after CSR: row end
__device__ int      g_total;             // scan ticket; zero at call start (agg2 re-zeros)
__device__ int      g_csrc[NE];
__device__ unsigned g_yb[(size_t)NN * (CH / 2)];  // (h @ W) * dinv, bf16x2 packed
__device__ float    g_h[(size_t)NN * CH];         // hidden activations (fp32)
__device__ int      g_gcnt[NG];          // zero at call start (scanoff re-zeros)

// ---- packed fp32x2 helpers (sm_100+) ----
__device__ __forceinline__ ull ffma2(ull a, ull b, ull c) {
    ull d; asm("fma.rn.f32x2 %0, %1, %2, %3;" : "=l"(d) : "l"(a), "l"(b), "l"(c));
    return d;
}
__device__ __forceinline__ ull fmul2(ull a, ull b) {
    ull d; asm("mul.rn.f32x2 %0, %1, %2;" : "=l"(d) : "l"(a), "l"(b));
    return d;
}
__device__ __forceinline__ ull bcast2(float x) {
    ull r; asm("mov.b64 %0, {%1, %1};" : "=l"(r) : "f"(x));
    return r;
}
__device__ __forceinline__ float2 unpack2(ull v) {
    float2 f; asm("mov.b64 {%0, %1}, %2;" : "=f"(f.x), "=f"(f.y) : "l"(v));
    return f;
}
// pack two fp32 -> bf16x2 (lo in low half), round-to-nearest
__device__ __forceinline__ unsigned pk_bf16x2(float lo, float hi) {
    unsigned r; asm("cvt.rn.bf16x2.f32 %0, %1, %2;" : "=r"(r) : "f"(hi), "f"(lo));
    return r;
}

__device__ __forceinline__ int load_id(const void* p, ll i, int is64) {
    if (is64) return (int)((const ll*)p)[i];
    return ((const int*)p)[i];
}

// per-warp dtype detection from edge_index src ids (uniform in [0,NN), so a
// zero odd-word is ~1e-5 for int32; all-zero for int64 upper halves)
__device__ __forceinline__ int detect64(const int* ei32) {
    int lane = threadIdx.x & 31;
    int v = __ldg(&ei32[2 * lane + 1]);
    unsigned m = __ballot_sync(0xffffffffu, v == 0);
    return __popc(m) >= 28;
}

// ---- degree histogram (2 edges/thread) + graph counts + is64 persist ----
__global__ void k_degcnt(const void* __restrict__ ei, const void* __restrict__ batch) {
    int is64 = detect64((const int*)ei);
    int t = blockIdx.x * blockDim.x + threadIdx.x;
    if (t == 0) g_is64 = is64;              // for later launches
    int e = t * 2;
    if (e < NE) {
        int d0, d1;
        if (is64) {
            longlong2 v = __ldg(&((const longlong2*)((const ll*)ei + NE))[t]);
            d0 = (int)v.x; d1 = (int)v.y;
        } else {
            int2 v = __ldg(&((const int2*)((const int*)ei + NE))[t]);
            d0 = v.x; d1 = v.y;
        }
        if ((unsigned)d0 < NN) atomicAdd(&g_degc[d0], 1);
        if (e + 1 < NE && (unsigned)d1 < NN) atomicAdd(&g_degc[d1], 1);
    }
    if (t < NN) {
        int g = load_id(batch, t, is64);
        if ((unsigned)g < NG) {
            unsigned act = __activemask();
            unsigned m = __match_any_sync(act, g);
            int leader = __ffs(m) - 1;
            if ((int)(threadIdx.x & 31) == leader) atomicAdd(&g_gcnt[g], __popc(m));
        }
    }
}

// ---- single-kernel scan: block shfl-scan + atomic region ticket ----
// Also: dinv, ginv (+gcnt re-zero), out prefill with bias.
__global__ void k_scanoff(const float* __restrict__ bout, float* __restrict__ out) {
    __shared__ int wsum[32];
    __shared__ int blkoff;
    int t = threadIdx.x;
    int i = blockIdx.x * 1024 + t;
    int v = (i < NN) ? g_degc[i] : 0;
    int s = v;
#pragma unroll
    for (int off = 1; off < 32; off <<= 1) {           // inclusive warp scan
        int n = __shfl_up_sync(0xffffffffu, s, off);
        if ((t & 31) >= off) s += n;
    }
    if ((t & 31) == 31) wsum[t >> 5] = s;
    __syncthreads();
    if (t < 32) {
        int w = wsum[t];
        int sw = w;
#pragma unroll
        for (int off = 1; off < 32; off <<= 1) {       // scan the 32 warp sums
            int n = __shfl_up_sync(0xffffffffu, sw, off);
            if (t >= off) sw += n;
        }
        wsum[t] = sw - w;                               // exclusive warp offset
        if (t == 31) blkoff = atomicAdd(&g_total, sw);  // region ticket (block total)
    }
    __syncthreads();
    if (i < NN) {
        g_rowptr[i] = blkoff + (s - v) + wsum[t >> 5];  // row start
        g_dinv[i] = rsqrtf((float)v + 1.0f);
    }
    if (i < NG) {
        g_ginv[i] = 1.0f / fmaxf((float)g_gcnt[i], 1.f);
        g_gcnt[i] = 0;                                  // ready for next call
        out[i] = bout[0];
    }
}

// ---- heterogeneous: blocks [0,GEMM_BLOCKS) do GEMM1; rest do CSR fill ----
// GEMM1: y[i,:] = (x[i,:] @ W1) * dinv[i], bf16 out -> g_yb
// CSR:   atomically bump g_rowptr[dst] to place src (rowptr[i] becomes row end)
__global__ void __launch_bounds__(256) k_csrgemm1(const float* __restrict__ xin,
                                                  const float* __restrict__ W,
                                                  const void* __restrict__ ei) {
    if (blockIdx.x < GEMM_BLOCKS) {
        __shared__ __align__(16) float Ws[CH * CH];
        int tid = threadIdx.x;
        for (int i = tid; i < CH * CH / 4; i += 256)
            ((float4*)Ws)[i] = ((const float4*)W)[i];
        __syncthreads();

        int cg = tid & 7;            // col group: cols [cg*8, cg*8+8)
        int rg = tid >> 3;           // row group 0..31
        int row0 = blockIdx.x * 256 + rg * 8;

        ull acc[8][4];
#pragma unroll
        for (int r = 0; r < 8; r++)
#pragma unroll
            for (int c = 0; c < 4; c++) acc[r][c] = 0ull;

        int rl[8];
#pragma unroll
        for (int r = 0; r < 8; r++) {
            int rr = row0 + r;
            rl[r] = (rr < NN) ? rr : (NN - 1);
        }

        const ull* Ws2 = (const ull*)Ws;
        for (int k0 = 0; k0 < CH; k0 += 4) {
            float4 xv[8];
#pragma unroll
            for (int r = 0; r < 8; r++)
                xv[r] = __ldg((const float4*)(xin + (size_t)rl[r] * CH + k0));
#pragma unroll
            for (int kk = 0; kk < 4; kk++) {
                ull wv[4];
#pragma unroll
                for (int c = 0; c < 4; c++)
                    wv[c] = Ws2[(k0 + kk) * (CH / 2) + cg * 4 + c];
#pragma unroll
                for (int r = 0; r < 8; r++) {
                    float xk = (kk == 0) ? xv[r].x : (kk == 1) ? xv[r].y
                             : (kk == 2) ? xv[r].z : xv[r].w;
                    ull xk2 = bcast2(xk);
#pragma unroll
                    for (int c = 0; c < 4; c++)
                        acc[r][c] = ffma2(xk2, wv[c], acc[r][c]);
                }
            }
        }

#pragma unroll
        for (int r = 0; r < 8; r++) {
            int rr = row0 + r;
            if (rr < NN) {
                ull d2 = bcast2(g_dinv[rr]);
                unsigned w[4];
#pragma unroll
                for (int c = 0; c < 4; c++) {
                    float2 v = unpack2(fmul2(acc[r][c], d2));
                    w[c] = pk_bf16x2(v.x, v.y);
                }
                ((uint4*)(g_yb + (size_t)rr * (CH / 2)))[cg] =
                    make_uint4(w[0], w[1], w[2], w[3]);
            }
        }
    } else {
        int t = (blockIdx.x - GEMM_BLOCKS) * 256 + threadIdx.x;
        int e = t * 2;
        if (e >= NE) return;
        int is64 = g_is64;
        int s0, s1, d0, d1;
        if (is64) {
            longlong2 sv = __ldg(&((const longlong2*)ei)[t]);
            longlong2 dv = __ldg(&((const longlong2*)((const ll*)ei + NE))[t]);
            s0 = (int)sv.x; s1 = (int)sv.y; d0 = (int)dv.x; d1 = (int)dv.y;
        } else {
            int2 sv = __ldg(&((const int2*)ei)[t]);
            int2 dv = __ldg(&((const int2*)((const int*)ei + NE))[t]);
            s0 = sv.x; s1 = sv.y; d0 = dv.x; d1 = dv.y;
        }
        if ((unsigned)d0 < NN && (unsigned)s0 < NN) {
            int p = atomicAdd(&g_rowptr[d0], 1);
            if ((unsigned)p < NE) g_csrc[p] = s0;
        }
        if (e + 1 < NE && (unsigned)d1 < NN && (unsigned)s1 < NN) {
            int p = atomicAdd(&g_rowptr[d1], 1);
            if ((unsigned)p < NE) g_csrc[p] = s1;
        }
    }
}

// bf16x2 word -> two fp32 (exact: shift into exponent position)
#define BF2X(w) __uint_as_float((w) << 16)
#define BF2Y(w) __uint_as_float((w) & 0xffff0000u)

// ---- layer-1 aggregate: h[i] = relu(dinv[i]*(sum_in y[src] + y[i]) + b1) ----
// After CSR fill: end = rowptr[i], start = end - degc[i].
__global__ void k_agg1(const float* __restrict__ b) {
    int i = (blockIdx.x * blockDim.x + threadIdx.x) >> 5;
    int lane = threadIdx.x & 31;
    if (i >= NN) return;

    const unsigned* __restrict__ yb = g_yb;
    unsigned ws = __ldg(&yb[(size_t)i * 32 + lane]);   // self loop
    float ax = BF2X(ws), ay = BF2Y(ws);
    int end = g_rowptr[i];
    int e = end - g_degc[i];
    for (; e + 4 <= end; e += 4) {
        int s0 = g_csrc[e], s1 = g_csrc[e + 1], s2 = g_csrc[e + 2], s3 = g_csrc[e + 3];
        unsigned w0 = __ldg(&yb[(size_t)s0 * 32 + lane]);
        unsigned w1 = __ldg(&yb[(size_t)s1 * 32 + lane]);
        unsigned w2 = __ldg(&yb[(size_t)s2 * 32 + lane]);
        unsigned w3 = __ldg(&yb[(size_t)s3 * 32 + lane]);
        ax += (BF2X(w0) + BF2X(w1)) + (BF2X(w2) + BF2X(w3));
        ay += (BF2Y(w0) + BF2Y(w1)) + (BF2Y(w2) + BF2Y(w3));
    }
    for (; e < end; e++) {
        int s = g_csrc[e];
        unsigned w = __ldg(&yb[(size_t)s * 32 + lane]);
        ax += BF2X(w); ay += BF2Y(w);
    }
    float d = g_dinv[i];
    float2 bb = ((const float2*)b)[lane];
    float2 h;
    h.x = fmaxf(fmaf(d, ax, bb.x), 0.f);
    h.y = fmaxf(fmaf(d, ay, bb.y), 0.f);
    ((float2*)(g_h + (size_t)i * CH))[lane] = h;
}

// ---- GEMM2: y[i,:] = (g_h[i,:] @ W2) * dinv[i], tiled FFMA2, bf16 -> g_yb ----
__global__ void __launch_bounds__(256) k_gemm2(const float* __restrict__ W) {
    __shared__ __align__(16) float Ws[CH * CH];
    const float* in = (const float*)g_h;
    int tid = threadIdx.x;
    for (int i = tid; i < CH * CH / 4; i += 256)
        ((float4*)Ws)[i] = ((const float4*)W)[i];
    __syncthreads();

    int cg = tid & 7;
    int rg = tid >> 3;
    int row0 = blockIdx.x * 256 + rg * 8;

    ull acc[8][4];
#pragma unroll
    for (int r = 0; r < 8; r++)
#pragma unroll
        for (int c = 0; c < 4; c++) acc[r][c] = 0ull;

    int rl[8];
#pragma unroll
    for (int r = 0; r < 8; r++) {
        int rr = row0 + r;
        rl[r] = (rr < NN) ? rr : (NN - 1);
    }

    const ull* Ws2 = (const ull*)Ws;
    for (int k0 = 0; k0 < CH; k0 += 4) {
        float4 xv[8];
#pragma unroll
        for (int r = 0; r < 8; r++)
            xv[r] = __ldg((const float4*)(in + (size_t)rl[r] * CH + k0));
#pragma unroll
        for (int kk = 0; kk < 4; kk++) {
            ull wv[4];
#pragma unroll
            for (int c = 0; c < 4; c++)
                wv[c] = Ws2[(k0 + kk) * (CH / 2) + cg * 4 + c];
#pragma unroll
            for (int r = 0; r < 8; r++) {
                float xk = (kk == 0) ? xv[r].x : (kk == 1) ? xv[r].y
                         : (kk == 2) ? xv[r].z : xv[r].w;
                ull xk2 = bcast2(xk);
#pragma unroll
                for (int c = 0; c < 4; c++)
                    acc[r][c] = ffma2(xk2, wv[c], acc[r][c]);
            }
        }
    }

#pragma unroll
    for (int r = 0; r < 8; r++) {
        int rr = row0 + r;
        if (rr < NN) {
            ull d2 = bcast2(g_dinv[rr]);
            unsigned w[4];
#pragma unroll
            for (int c = 0; c < 4; c++) {
                float2 v = unpack2(fmul2(acc[r][c], d2));
                w[c] = pk_bf16x2(v.x, v.y);
            }
            ((uint4*)(g_yb + (size_t)rr * (CH / 2)))[cg] =
                make_uint4(w[0], w[1], w[2], w[3]);
        }
    }
}

// ---- layer-2 aggregate + Wout dot + mean-pool atomic + state re-zero ----
__global__ void k_agg2(const float* __restrict__ b,
                       const float* __restrict__ Wout,
                       const void* __restrict__ batch,
                       float* __restrict__ out) {
    int i = (blockIdx.x * blockDim.x + threadIdx.x) >> 5;
    int lane = threadIdx.x & 31;
    if (i >= NN) return;

    const unsigned* __restrict__ yb = g_yb;
    unsigned ws = __ldg(&yb[(size_t)i * 32 + lane]);
    float ax = BF2X(ws), ay = BF2Y(ws);
    int end = g_rowptr[i];
    int deg = g_degc[i];
    int e = end - deg;
    for (; e + 4 <= end; e += 4) {
        int s0 = g_csrc[e], s1 = g_csrc[e + 1], s2 = g_csrc[e + 2], s3 = g_csrc[e + 3];
        unsigned w0 = __ldg(&yb[(size_t)s0 * 32 + lane]);
        unsigned w1 = __ldg(&yb[(size_t)s1 * 32 + lane]);
        unsigned w2 = __ldg(&yb[(size_t)s2 * 32 + lane]);
        unsigned w3 = __ldg(&yb[(size_t)s3 * 32 + lane]);
        ax += (BF2X(w0) + BF2X(w1)) + (BF2X(w2) + BF2X(w3));
        ay += (BF2Y(w0) + BF2Y(w1)) + (BF2Y(w2) + BF2Y(w3));
    }
    for (; e < end; e++) {
        int s = g_csrc[e];
        unsigned w = __ldg(&yb[(size_t)s * 32 + lane]);
        ax += BF2X(w); ay += BF2Y(w);
    }
    float d = g_dinv[i];
    float2 bb = ((const float2*)b)[lane];
    float hx = fmaxf(fmaf(d, ax, bb.x), 0.f);
    float hy = fmaxf(fmaf(d, ay, bb.y), 0.f);
    float2 wo = ((const float2*)Wout)[lane];
    float s = hx * wo.x + hy * wo.y;
#pragma unroll
    for (int off = 16; off; off >>= 1) s += __shfl_xor_sync(0xffffffffu, s, off);
    if (lane == 0) {
        int g = load_id(batch, i, g_is64);
        if ((unsigned)g < NG) atomicAdd(&out[g], s * g_ginv[g]);
        g_degc[i] = 0;                                  // ready for next call
        if (i == 0) g_total = 0;                        // reset scan ticket
    }
}

extern "C" void kernel_launch(void* const* d_in, const int* in_sizes, int n_in,
                              void* d_out, int out_size) {
    const float* x     = (const float*)d_in[0];
    const void*  ei    = d_in[1];
    const void*  batch = d_in[2];
    const float* W1    = (const float*)d_in[3];
    const float* b1    = (const float*)d_in[4];
    const float* W2    = (const float*)d_in[5];
    const float* b2    = (const float*)d_in[6];
    const float* Wout  = (const float*)d_in[7];
    const float* bout  = (const float*)d_in[8];
    float*       out   = (float*)d_out;

    (void)in_sizes; (void)n_in; (void)out_size;

    k_degcnt  <<<(NE / 2 + 255) / 256, 256>>>(ei, batch);
    k_scanoff <<<(NN + 1023) / 1024, 1024>>>(bout, out);
    k_csrgemm1<<<GEMM_BLOCKS + CSR_BLOCKS, 256>>>(x, W1, ei);    // GEMM1 ∥ CSR fill
    k_agg1    <<<(NN * 32 + 255) / 256, 256>>>(b1);
    k_gemm2   <<<(NN + 255) / 256, 256>>>(W2);
    k_agg2    <<<(NN * 32 + 255) / 256, 256>>>(b2, Wout, batch, out);
}